// round 1
// baseline (speedup 1.0000x reference)
#include <cuda_runtime.h>

// ---------------------------------------------------------------------------
// MultimodalRegionAwareAttention — fp32 baseline
//
// Stage 1 (repack): grid layout [B,C,16,16,16] -> seq layout
//   scratch[mod][b][h][region][r][pos]   (r = head_dim index, pos = region cube)
//   Q is pre-scaled by HEAD_DIM^-0.5. Both global read and write are float4.
//
// Stage 2 (attention): CTA per (qmod, b, h, region). 256 threads, 4x4 register
//   tiling (16x16 thread grid over the 64x64 tile). 16 key tiles (4 modalities
//   x topk 4), online softmax. Smem: Q[64][64], K[64][64], V[64][68], P[64][68].
// ---------------------------------------------------------------------------

#define BQ    2
#define NH    4
#define NREG  64
#define RC    64     // region cube (pos)
#define HDIM  64
#define TOPK  4
#define NMOD  4

// per-(mod,b,h) block is 64 regions * 64 r * 64 pos = 262144 floats
#define MBH_STRIDE 262144

// 3 x 33.5 MB static scratch (allocation-free rule: __device__ globals).
__device__ float g_qs[NMOD * BQ * NH * NREG * HDIM * RC];
__device__ float g_ks[NMOD * BQ * NH * NREG * HDIM * RC];
__device__ float g_vs[NMOD * BQ * NH * NREG * HDIM * RC];

struct Ptrs12 { const float4* p[12]; };

// ---------------------------------------------------------------------------
// Repack: one CTA per (tensor t in 0..11, b, c). 4096 floats per CTA.
// src element (b,c,hh,ww,dd) -> dst (mod,b,h,n,r,pos) with
//   h = c/64, r = c%64, n = (hh/4)*16+(ww/4)*4+(dd/4), pos = (hh%4)*16+(ww%4)*4+(dd%4)
// A float4 over dd (dd%4==0 base) maps to a float4 over pos. Fully coalesced.
// ---------------------------------------------------------------------------
__global__ void repack_kernel(Ptrs12 ptrs) {
    const int c    = blockIdx.x;        // 0..255
    const int b    = blockIdx.y;        // 0..1
    const int t    = blockIdx.z;        // 0..11
    const int mod  = t & 3;
    const int kind = t >> 2;            // 0=q 1=k 2=v
    const int h    = c >> 6;
    const int r    = c & 63;

    const float4* src = ptrs.p[t] + (size_t)(b * 256 + c) * 1024;
    float* base = (kind == 0 ? g_qs : (kind == 1 ? g_ks : g_vs));
    float* dst  = base + (size_t)((mod * BQ + b) * NH + h) * MBH_STRIDE + r * RC;
    const float scale = (kind == 0) ? 0.125f : 1.0f;   // HEAD_DIM^-0.5 folded into Q

    #pragma unroll
    for (int it = 0; it < 4; it++) {
        int cid = threadIdx.x + it * 256;          // 0..1023 float4 chunks
        float4 v = src[cid];
        int dblk = cid & 3;
        int ww   = (cid >> 2) & 15;
        int hh   = cid >> 6;
        int n    = (hh >> 2) * 16 + (ww >> 2) * 4 + dblk;
        int posb = (hh & 3) * 16 + (ww & 3) * 4;
        v.x *= scale; v.y *= scale; v.z *= scale; v.w *= scale;
        *(float4*)(dst + n * (HDIM * RC) + posb) = v;
    }
}

// ---------------------------------------------------------------------------
// Attention kernel
// ---------------------------------------------------------------------------
#define VP_STRIDE 68    // padded row stride for Vs / Ps
#define SMEM_FLOATS (64*64 + 64*64 + 64*VP_STRIDE + 64*VP_STRIDE)

__global__ void __launch_bounds__(256, 2)
attn_kernel(const int* __restrict__ mask,
            const int* __restrict__ rg0, const int* __restrict__ rg1,
            const int* __restrict__ rg2, const int* __restrict__ rg3,
            float* __restrict__ out) {
    extern __shared__ float sm[];
    float* Qs = sm;                    // [r][pos]   64x64
    float* Ks = Qs + 64 * 64;          // [r][kpos]  64x64
    float* Vs = Ks + 64 * 64;          // [kpos][r]  64x68
    float* Ps = Vs + 64 * VP_STRIDE;   // [kpos][qpos] 64x68

    const int bhn = blockIdx.x;        // 0..511
    const int qm  = blockIdx.y;        // 0..3
    const int b   = bhn >> 8;
    const int h   = (bhn >> 6) & 3;
    const int n   = bhn & 63;

    const int tid = threadIdx.x;
    const int tx  = tid & 15;          // column group (keys / head_dim)
    const int ty  = tid >> 4;          // row group (query pos)

    const int* rgs[4] = { rg0, rg1, rg2, rg3 };

    // --- load Q tile (already scaled) ---
    {
        const float4* qsrc = (const float4*)(g_qs
            + (size_t)((qm * BQ + b) * NH + h) * MBH_STRIDE + n * (HDIM * RC));
        float4* q4 = (float4*)Qs;
        #pragma unroll
        for (int it = 0; it < 4; it++) q4[tid + it * 256] = qsrc[tid + it * 256];
    }

    float O[4][4] = {};
    float m_r[4], l_r[4];
    #pragma unroll
    for (int i = 0; i < 4; i++) { m_r[i] = -1e30f; l_r[i] = 0.0f; }

    const size_t kv_mbh_off = (size_t)(b * NH + h) * MBH_STRIDE;
    const int rg_off = ((b * NH + h) * NREG + n) * TOPK;

    for (int mkv = 0; mkv < NMOD; mkv++) {
        if (mask[b * NMOD + mkv] == 0) continue;   // whole modality masked out
        const int* rg = rgs[mkv];
        const size_t mod_off = (size_t)mkv * BQ * NH * MBH_STRIDE + kv_mbh_off;

        for (int tk = 0; tk < TOPK; tk++) {
            const int region = rg[rg_off + tk];
            const float4* ksrc = (const float4*)(g_ks + mod_off + (size_t)region * (HDIM * RC));
            const float4* vsrc = (const float4*)(g_vs + mod_off + (size_t)region * (HDIM * RC));

            __syncthreads();   // previous GEMMs done with Ks / Vs
            #pragma unroll
            for (int it = 0; it < 4; it++) {
                int cid = tid + it * 256;
                ((float4*)Ks)[cid] = ksrc[cid];
                float4 vv = vsrc[cid];          // [r][pos]: r = cid>>4, pos = 4*(cid&15)..+3
                int r  = cid >> 4;
                int pc = cid & 15;
                Vs[(4 * pc + 0) * VP_STRIDE + r] = vv.x;   // transpose to [pos][r]
                Vs[(4 * pc + 1) * VP_STRIDE + r] = vv.y;
                Vs[(4 * pc + 2) * VP_STRIDE + r] = vv.z;
                Vs[(4 * pc + 3) * VP_STRIDE + r] = vv.w;
            }
            __syncthreads();

            // --- S = Q @ K^T  (64x64x64, 4x4 per thread) ---
            float S[4][4] = {};
            #pragma unroll 4
            for (int r = 0; r < 64; r++) {
                float4 a  = *(const float4*)(Qs + r * 64 + 4 * ty);   // broadcast
                float4 k4 = *(const float4*)(Ks + r * 64 + 4 * tx);
                float av[4] = { a.x, a.y, a.z, a.w };
                float kv[4] = { k4.x, k4.y, k4.z, k4.w };
                #pragma unroll
                for (int i = 0; i < 4; i++)
                    #pragma unroll
                    for (int j = 0; j < 4; j++)
                        S[i][j] = fmaf(av[i], kv[j], S[i][j]);
            }

            // --- online softmax (rows owned by 16 lanes of a half-warp) ---
            #pragma unroll
            for (int i = 0; i < 4; i++) {
                float tm = fmaxf(fmaxf(S[i][0], S[i][1]), fmaxf(S[i][2], S[i][3]));
                #pragma unroll
                for (int off = 8; off >= 1; off >>= 1)
                    tm = fmaxf(tm, __shfl_xor_sync(0xffffffffu, tm, off));
                float mn = fmaxf(m_r[i], tm);
                float alpha = __expf(m_r[i] - mn);
                float rs = 0.0f;
                #pragma unroll
                for (int j = 0; j < 4; j++) {
                    float p = __expf(S[i][j] - mn);
                    S[i][j] = p;
                    rs += p;
                }
                #pragma unroll
                for (int off = 8; off >= 1; off >>= 1)
                    rs += __shfl_xor_sync(0xffffffffu, rs, off);
                l_r[i] = l_r[i] * alpha + rs;
                m_r[i] = mn;
                #pragma unroll
                for (int j = 0; j < 4; j++) O[i][j] *= alpha;
            }

            // --- stash P to smem: Ps[kpos][qpos] ---
            #pragma unroll
            for (int jj = 0; jj < 4; jj++) {
                float4 pv = make_float4(S[0][jj], S[1][jj], S[2][jj], S[3][jj]);
                *(float4*)(Ps + (4 * tx + jj) * VP_STRIDE + 4 * ty) = pv;
            }
            __syncthreads();

            // --- O += P @ V  (64x64x64) ---
            #pragma unroll 4
            for (int j = 0; j < 64; j++) {
                float4 a  = *(const float4*)(Ps + j * VP_STRIDE + 4 * ty);  // broadcast
                float4 v4 = *(const float4*)(Vs + j * VP_STRIDE + 4 * tx);
                float av[4] = { a.x, a.y, a.z, a.w };
                float vv[4] = { v4.x, v4.y, v4.z, v4.w };
                #pragma unroll
                for (int i = 0; i < 4; i++)
                    #pragma unroll
                    for (int jj = 0; jj < 4; jj++)
                        O[i][jj] = fmaf(av[i], vv[jj], O[i][jj]);
            }
        }
    }

    // --- epilogue: O/l, scatter back to grid layout ---
    float inv[4];
    #pragma unroll
    for (int i = 0; i < 4; i++) inv[i] = 1.0f / l_r[i];

    const int hblk = n >> 4, wblk = (n >> 2) & 3, dblk = n & 3;
    // pos = 4*ty + i  ->  p = ty/4, qq = ty%4, rr = i (contiguous float4 over dd)
    const int spat = (hblk * 4 + (ty >> 2)) * 256 + (wblk * 4 + (ty & 3)) * 16 + dblk * 4;
    const size_t obase = (size_t)((qm * BQ + b) * 256 + h * 64) * 4096;

    #pragma unroll
    for (int jj = 0; jj < 4; jj++) {
        float4 o = make_float4(O[0][jj] * inv[0], O[1][jj] * inv[1],
                               O[2][jj] * inv[2], O[3][jj] * inv[3]);
        *(float4*)(out + obase + (size_t)(4 * tx + jj) * 4096 + spat) = o;
    }
}

// ---------------------------------------------------------------------------
// Launch
// ---------------------------------------------------------------------------
extern "C" void kernel_launch(void* const* d_in, const int* in_sizes, int n_in,
                              void* d_out, int out_size) {
    (void)in_sizes; (void)n_in; (void)out_size;

    // d_in order (metadata): mask, q0..q3, k0..k3, v0..v3, rg0..rg3
    Ptrs12 ptrs;
    for (int i = 0; i < 12; i++) ptrs.p[i] = (const float4*)d_in[1 + i];

    dim3 rgrid(256, BQ, 12);
    repack_kernel<<<rgrid, 256>>>(ptrs);

    const int smem_bytes = SMEM_FLOATS * (int)sizeof(float);   // 67584
    cudaFuncSetAttribute(attn_kernel,
                         cudaFuncAttributeMaxDynamicSharedMemorySize, smem_bytes);

    dim3 agrid(BQ * NH * NREG, NMOD);   // (512, 4)
    attn_kernel<<<agrid, 256, smem_bytes>>>(
        (const int*)d_in[0],
        (const int*)d_in[13], (const int*)d_in[14],
        (const int*)d_in[15], (const int*)d_in[16],
        (float*)d_out);
}

// round 4
// speedup vs baseline: 4.6302x; 4.6302x over previous
#include <cuda_runtime.h>
#include <cstdint>

// ---------------------------------------------------------------------------
// MultimodalRegionAwareAttention — tf32 mma.sync version (race-fixed)
//
// repack:  q,k -> [mod][b][h][n][r][pos] (tf32-rounded; q scaled by 1/8*log2e)
//          v   -> [mod][b][h][n][pos][r] (transposed, tf32-rounded)
// attn:    CTA = (b,h,n) x qm-pair. M=128 q-rows share gathered K/V (1024 keys
//          in 16 tiles of 64). tf32 m16n8k8 for S=QK^T and O+=PV, online
//          softmax in accum registers, P->A-fragment via quad shuffles,
//          double-buffered cp.async K/V with end-of-iteration barrier (WAR).
// ---------------------------------------------------------------------------

#define BQ    2
#define NH    4
#define NREG  64
#define RC    64
#define HDIM  64
#define TOPK  4
#define NMOD  4
#define MBH_STRIDE 262144            // 64 regions * 64 * 64
#define QSC 0.18033688011112042f     // (1/sqrt(64)) * log2(e)

__device__ float g_qs[NMOD * BQ * NH * NREG * HDIM * RC];
__device__ float g_ks[NMOD * BQ * NH * NREG * HDIM * RC];
__device__ float g_vs[NMOD * BQ * NH * NREG * HDIM * RC];

__device__ __forceinline__ float tf32r(float x) {
    unsigned u;
    asm("cvt.rna.tf32.f32 %0, %1;" : "=r"(u) : "f"(x));
    return __uint_as_float(u);
}

__device__ __forceinline__ uint32_t smaddr(const void* p) {
    return (uint32_t)__cvta_generic_to_shared(p);
}

#define CP16(dst, src) \
    asm volatile("cp.async.cg.shared.global [%0], [%1], 16;" :: "r"(dst), "l"(src))

#define MMA_TF32(c, a0, a1, a2, a3, b0, b1)                                    \
    asm volatile(                                                              \
        "mma.sync.aligned.m16n8k8.row.col.f32.tf32.tf32.f32 "                  \
        "{%0,%1,%2,%3},{%4,%5,%6,%7},{%8,%9},{%0,%1,%2,%3};"                   \
        : "+f"((c)[0]), "+f"((c)[1]), "+f"((c)[2]), "+f"((c)[3])               \
        : "r"(a0), "r"(a1), "r"(a2), "r"(a3),                                  \
          "r"(__float_as_uint(b0)), "r"(__float_as_uint(b1)))

// ---------------------------------------------------------------------------
// q/k repack (q: scale+round, k: round). Layout [n][r][pos], fully coalesced.
// ---------------------------------------------------------------------------
struct Ptrs8 { const float4* p[8]; };

__global__ void qk_repack(Ptrs8 ptrs) {
    const int c    = blockIdx.x;       // 0..255
    const int b    = blockIdx.y;       // 0..1
    const int t    = blockIdx.z;       // 0..7 (q0..3, k0..3)
    const int mod  = t & 3;
    const int kind = t >> 2;
    const int h = c >> 6, r = c & 63;

    const float4* src = ptrs.p[t] + (size_t)(b * 256 + c) * 1024;
    float* base = kind == 0 ? g_qs : g_ks;
    float* dst  = base + (size_t)((mod * BQ + b) * NH + h) * MBH_STRIDE + r * RC;
    const float scale = (kind == 0) ? QSC : 1.0f;

    #pragma unroll
    for (int it = 0; it < 4; it++) {
        int cid = threadIdx.x + it * 256;
        float4 v = src[cid];
        int dblk = cid & 3, ww = (cid >> 2) & 15, hh = cid >> 6;
        int n    = (hh >> 2) * 16 + (ww >> 2) * 4 + dblk;
        int posb = (hh & 3) * 16 + (ww & 3) * 4;
        v.x = tf32r(v.x * scale); v.y = tf32r(v.y * scale);
        v.z = tf32r(v.z * scale); v.w = tf32r(v.w * scale);
        *(float4*)(dst + n * 4096 + posb) = v;
    }
}

// ---------------------------------------------------------------------------
// v repack with transpose: grid (n=64, b*h=8, mod=4) -> [pos][r]
// ---------------------------------------------------------------------------
__global__ void v_repack(const float4* v0, const float4* v1,
                         const float4* v2, const float4* v3) {
    __shared__ float sm[64 * 65];
    const int n = blockIdx.x, bh = blockIdx.y, mod = blockIdx.z;
    const int b = bh >> 2, h = bh & 3;
    const float4* src = (mod == 0) ? v0 : (mod == 1) ? v1 : (mod == 2) ? v2 : v3;
    const int hblk = n >> 4, wblk = (n >> 2) & 3, dblk = n & 3;
    const int tid = threadIdx.x;

    #pragma unroll
    for (int i = 0; i < 4; i++) {
        int c = tid + i * 256;                 // 0..1023
        int r = c >> 4, pq = c & 15;
        int pl = pq >> 2, ql = pq & 3;
        int sidx = (((b * 256 + h * 64 + r) * 4096) +
                    (hblk * 4 + pl) * 256 + (wblk * 4 + ql) * 16 + dblk * 4) >> 2;
        float4 v = src[sidx];
        int pos = pq * 4;
        sm[r * 65 + pos + 0] = tf32r(v.x);
        sm[r * 65 + pos + 1] = tf32r(v.y);
        sm[r * 65 + pos + 2] = tf32r(v.z);
        sm[r * 65 + pos + 3] = tf32r(v.w);
    }
    __syncthreads();

    float* dst = g_vs + (size_t)((mod * BQ + b) * NH + h) * MBH_STRIDE + n * 4096;
    #pragma unroll
    for (int i = 0; i < 4; i++) {
        int c = tid + i * 256;
        int pos = c >> 4, r4 = (c & 15) * 4;
        float4 o;
        o.x = sm[(r4 + 0) * 65 + pos];
        o.y = sm[(r4 + 1) * 65 + pos];
        o.z = sm[(r4 + 2) * 65 + pos];
        o.w = sm[(r4 + 3) * 65 + pos];
        *(float4*)(dst + pos * 64 + r4) = o;
    }
}

// ---------------------------------------------------------------------------
// Attention
// ---------------------------------------------------------------------------
#define SK 68                         // K/V smem row stride (floats)
#define SQ 136                        // Q smem row stride (floats)
#define QS_FLOATS (64 * SQ)           // 8704
#define KV_FLOATS (64 * SK)           // 4352
#define SMEM_BYTES ((QS_FLOATS + 4 * KV_FLOATS) * 4)   // 104448

__global__ void __launch_bounds__(256, 2)
attn(const int* __restrict__ mask,
     const int* __restrict__ rg0, const int* __restrict__ rg1,
     const int* __restrict__ rg2, const int* __restrict__ rg3,
     float* __restrict__ out) {
    extern __shared__ float sm[];
    float* Qs = sm;
    float* Kb0 = sm + QS_FLOATS;
    float* Kb1 = Kb0 + KV_FLOATS;
    float* Vb0 = Kb1 + KV_FLOATS;
    float* Vb1 = Vb0 + KV_FLOATS;
    __shared__ int s_off[16];
    __shared__ int s_T;

    const int bhn = blockIdx.x;                 // 0..511
    const int qp  = blockIdx.y;                 // q-mod pair 0..1
    const int b = bhn >> 8, h = (bhn >> 6) & 3, n = bhn & 63;

    const int tid  = threadIdx.x;
    const int w    = tid >> 5;
    const int lane = tid & 31;
    const int g    = lane >> 2;
    const int t4   = lane & 3;

    // tile list (mask-compacted) by thread 0
    if (tid == 0) {
        const int* rgs[4] = { rg0, rg1, rg2, rg3 };
        int T = 0;
        const int rbase = ((b * NH + h) * NREG + n) * TOPK;
        for (int m = 0; m < 4; m++) {
            if (mask[b * 4 + m] != 0) {
                int mb = ((m * BQ + b) * NH + h) * MBH_STRIDE;
                for (int tk = 0; tk < 4; tk++)
                    s_off[T++] = mb + rgs[m][rbase + tk] * 4096;
            }
        }
        s_T = T;
    }

    // Q -> smem [r][m], m = qm_local*64 + pos (part of cp.async group 0)
    {
        uint32_t qsb = smaddr(Qs);
        #pragma unroll
        for (int mm = 0; mm < 2; mm++) {
            const char* src = (const char*)(g_qs
                + (size_t)(((qp * 2 + mm) * BQ + b) * NH + h) * MBH_STRIDE
                + (size_t)n * 4096);
            #pragma unroll
            for (int i = 0; i < 4; i++) {
                int c = tid + i * 256;
                int r = c >> 4, pq = c & 15;
                CP16(qsb + (uint32_t)((r * SQ + mm * 64 + pq * 4) * 4), src + c * 16);
            }
        }
    }
    __syncthreads();                 // s_off/s_T visible
    const int T = s_T;

    float* Kbuf[2] = { Kb0, Kb1 };
    float* Vbuf[2] = { Vb0, Vb1 };

    auto prefetch = [&](int t) {
        const int off = s_off[t];
        const char* ks = (const char*)(g_ks + off);
        const char* vs = (const char*)(g_vs + off);
        uint32_t kb = smaddr(Kbuf[t & 1]);
        uint32_t vb = smaddr(Vbuf[t & 1]);
        #pragma unroll
        for (int i = 0; i < 4; i++) {
            int c = tid + i * 256;
            int r = c >> 4;
            uint32_t cb = (uint32_t)((c & 15) * 16);
            CP16(kb + (uint32_t)(r * SK * 4) + cb, ks + c * 16);
            int vr = ((r & 7) << 3) | (r >> 3);          // 8x8 row swizzle
            CP16(vb + (uint32_t)(vr * SK * 4) + cb, vs + c * 16);
        }
    };

    if (T > 0) prefetch(0);
    asm volatile("cp.async.commit_group;");

    float cS[8][4];
    float o[8][4];
    #pragma unroll
    for (int nn = 0; nn < 8; nn++)
        #pragma unroll
        for (int j = 0; j < 4; j++) o[nn][j] = 0.0f;
    float m0 = -1e30f, m1 = -1e30f, l0 = 0.0f, l1 = 0.0f;

    const int qcol = w * 16 + g;
    const int sA = (lane & ~3) | (t4 >> 1);
    const int sB = sA + 2;
    const bool odd = (t4 & 1) != 0;

    for (int t = 0; t < T; t++) {
        // WAR safety: all warps finished reading buf[(t+1)&1] (used at t-1)
        // before we overwrite it. (At t==0 this is the post-init barrier.)
        if (t > 0) __syncthreads();

        if (t + 1 < T) prefetch(t + 1);
        asm volatile("cp.async.commit_group;");
        asm volatile("cp.async.wait_group 1;");
        __syncthreads();             // buf[t&1] data visible to all warps

        const float* K = Kbuf[t & 1];
        const float* V = Vbuf[t & 1];

        // ---- S = Q @ K^T (tile nn col c <-> key 8c+nn) ----
        #pragma unroll
        for (int nn = 0; nn < 8; nn++)
            #pragma unroll
            for (int j = 0; j < 4; j++) cS[nn][j] = 0.0f;

        #pragma unroll
        for (int kk = 0; kk < 8; kk++) {
            const int r0 = kk * 8 + t4;
            uint32_t a0 = __float_as_uint(Qs[r0 * SQ + qcol]);
            uint32_t a1 = __float_as_uint(Qs[r0 * SQ + qcol + 8]);
            uint32_t a2 = __float_as_uint(Qs[(r0 + 4) * SQ + qcol]);
            uint32_t a3 = __float_as_uint(Qs[(r0 + 4) * SQ + qcol + 8]);
            float4 b0lo = *(const float4*)(K + r0 * SK + 8 * g);
            float4 b0hi = *(const float4*)(K + r0 * SK + 8 * g + 4);
            float4 b1lo = *(const float4*)(K + (r0 + 4) * SK + 8 * g);
            float4 b1hi = *(const float4*)(K + (r0 + 4) * SK + 8 * g + 4);
            MMA_TF32(cS[0], a0, a1, a2, a3, b0lo.x, b1lo.x);
            MMA_TF32(cS[1], a0, a1, a2, a3, b0lo.y, b1lo.y);
            MMA_TF32(cS[2], a0, a1, a2, a3, b0lo.z, b1lo.z);
            MMA_TF32(cS[3], a0, a1, a2, a3, b0lo.w, b1lo.w);
            MMA_TF32(cS[4], a0, a1, a2, a3, b0hi.x, b1hi.x);
            MMA_TF32(cS[5], a0, a1, a2, a3, b0hi.y, b1hi.y);
            MMA_TF32(cS[6], a0, a1, a2, a3, b0hi.z, b1hi.z);
            MMA_TF32(cS[7], a0, a1, a2, a3, b0hi.w, b1hi.w);
        }

        // ---- online softmax (rows g, g+8; quad reduce over t4) ----
        float mx0 = -1e30f, mx1 = -1e30f;
        #pragma unroll
        for (int nn = 0; nn < 8; nn++) {
            mx0 = fmaxf(mx0, fmaxf(cS[nn][0], cS[nn][1]));
            mx1 = fmaxf(mx1, fmaxf(cS[nn][2], cS[nn][3]));
        }
        mx0 = fmaxf(mx0, __shfl_xor_sync(0xffffffffu, mx0, 1));
        mx0 = fmaxf(mx0, __shfl_xor_sync(0xffffffffu, mx0, 2));
        mx1 = fmaxf(mx1, __shfl_xor_sync(0xffffffffu, mx1, 1));
        mx1 = fmaxf(mx1, __shfl_xor_sync(0xffffffffu, mx1, 2));
        const float nm0 = fmaxf(m0, mx0), nm1 = fmaxf(m1, mx1);
        const float al0 = exp2f(m0 - nm0), al1 = exp2f(m1 - nm1);
        m0 = nm0; m1 = nm1;

        float rs0 = 0.0f, rs1 = 0.0f;
        #pragma unroll
        for (int nn = 0; nn < 8; nn++) {
            cS[nn][0] = exp2f(cS[nn][0] - nm0);
            cS[nn][1] = exp2f(cS[nn][1] - nm0);
            cS[nn][2] = exp2f(cS[nn][2] - nm1);
            cS[nn][3] = exp2f(cS[nn][3] - nm1);
            rs0 += cS[nn][0] + cS[nn][1];
            rs1 += cS[nn][2] + cS[nn][3];
        }
        rs0 += __shfl_xor_sync(0xffffffffu, rs0, 1);
        rs0 += __shfl_xor_sync(0xffffffffu, rs0, 2);
        rs1 += __shfl_xor_sync(0xffffffffu, rs1, 1);
        rs1 += __shfl_xor_sync(0xffffffffu, rs1, 2);
        l0 = l0 * al0 + rs0;
        l1 = l1 * al1 + rs1;

        #pragma unroll
        for (int nn = 0; nn < 8; nn++) {
            o[nn][0] *= al0; o[nn][1] *= al0;
            o[nn][2] *= al1; o[nn][3] *= al1;
        }

        // round P to tf32 (fp32 l already captured)
        #pragma unroll
        for (int nn = 0; nn < 8; nn++)
            #pragma unroll
            for (int j = 0; j < 4; j++) cS[nn][j] = tf32r(cS[nn][j]);

        // ---- O += P @ V  (A frags from accum via quad shuffles) ----
        #pragma unroll
        for (int kk = 0; kk < 8; kk++) {
            float p0A = __shfl_sync(0xffffffffu, cS[kk][0], sA);
            float p1A = __shfl_sync(0xffffffffu, cS[kk][1], sA);
            float p2A = __shfl_sync(0xffffffffu, cS[kk][2], sA);
            float p3A = __shfl_sync(0xffffffffu, cS[kk][3], sA);
            float p0B = __shfl_sync(0xffffffffu, cS[kk][0], sB);
            float p1B = __shfl_sync(0xffffffffu, cS[kk][1], sB);
            float p2B = __shfl_sync(0xffffffffu, cS[kk][2], sB);
            float p3B = __shfl_sync(0xffffffffu, cS[kk][3], sB);
            uint32_t a0 = __float_as_uint(odd ? p1A : p0A);
            uint32_t a1 = __float_as_uint(odd ? p3A : p2A);
            uint32_t a2 = __float_as_uint(odd ? p1B : p0B);
            uint32_t a3 = __float_as_uint(odd ? p3B : p2B);
            const int vr = kk * 8 + t4;                 // swizzled: key 8*t4+kk
            float4 b0lo = *(const float4*)(V + vr * SK + 8 * g);
            float4 b0hi = *(const float4*)(V + vr * SK + 8 * g + 4);
            float4 b1lo = *(const float4*)(V + (vr + 4) * SK + 8 * g);
            float4 b1hi = *(const float4*)(V + (vr + 4) * SK + 8 * g + 4);
            MMA_TF32(o[0], a0, a1, a2, a3, b0lo.x, b1lo.x);
            MMA_TF32(o[1], a0, a1, a2, a3, b0lo.y, b1lo.y);
            MMA_TF32(o[2], a0, a1, a2, a3, b0lo.z, b1lo.z);
            MMA_TF32(o[3], a0, a1, a2, a3, b0lo.w, b1lo.w);
            MMA_TF32(o[4], a0, a1, a2, a3, b0hi.x, b1hi.x);
            MMA_TF32(o[5], a0, a1, a2, a3, b0hi.y, b1hi.y);
            MMA_TF32(o[6], a0, a1, a2, a3, b0hi.z, b1hi.z);
            MMA_TF32(o[7], a0, a1, a2, a3, b0hi.w, b1hi.w);
        }
    }

    // ---- epilogue: normalize + scatter (hd = 8*col + nn un-permutes) ----
    const float i0 = 1.0f / l0, i1 = 1.0f / l1;
    const int qm_l = w >> 2;
    const int pos0 = (w & 3) * 16 + g;
    const int pos1 = pos0 + 8;
    const int hblk = n >> 4, wblk = (n >> 2) & 3, dblk = n & 3;
    const int sp0 = (hblk * 4 + (pos0 >> 4)) * 256 + (wblk * 4 + ((pos0 >> 2) & 3)) * 16
                    + dblk * 4 + (pos0 & 3);
    const int sp1 = (hblk * 4 + (pos1 >> 4)) * 256 + (wblk * 4 + ((pos1 >> 2) & 3)) * 16
                    + dblk * 4 + (pos1 & 3);
    const size_t obase = (size_t)(((qp * 2 + qm_l) * BQ + b) * 256 + h * 64) * 4096;

    #pragma unroll
    for (int nn = 0; nn < 8; nn++) {
        const int hd0 = 8 * (2 * t4) + nn;
        const int hd1 = 8 * (2 * t4 + 1) + nn;
        out[obase + (size_t)hd0 * 4096 + sp0] = o[nn][0] * i0;
        out[obase + (size_t)hd1 * 4096 + sp0] = o[nn][1] * i0;
        out[obase + (size_t)hd0 * 4096 + sp1] = o[nn][2] * i1;
        out[obase + (size_t)hd1 * 4096 + sp1] = o[nn][3] * i1;
    }
}

// ---------------------------------------------------------------------------
// Launch
// ---------------------------------------------------------------------------
extern "C" void kernel_launch(void* const* d_in, const int* in_sizes, int n_in,
                              void* d_out, int out_size) {
    (void)in_sizes; (void)n_in; (void)out_size;

    // d_in: mask, q0..q3, k0..k3, v0..v3, rg0..rg3
    Ptrs8 qk;
    for (int i = 0; i < 8; i++) qk.p[i] = (const float4*)d_in[1 + i];

    dim3 rgrid(256, BQ, 8);
    qk_repack<<<rgrid, 256>>>(qk);

    dim3 vgrid(64, 8, 4);
    v_repack<<<vgrid, 256>>>((const float4*)d_in[9], (const float4*)d_in[10],
                             (const float4*)d_in[11], (const float4*)d_in[12]);

    cudaFuncSetAttribute(attn, cudaFuncAttributeMaxDynamicSharedMemorySize,
                         SMEM_BYTES);
    dim3 agrid(BQ * NH * NREG, 2);          // (512, 2)
    attn<<<agrid, 256, SMEM_BYTES>>>(
        (const int*)d_in[0],
        (const int*)d_in[13], (const int*)d_in[14],
        (const int*)d_in[15], (const int*)d_in[16],
        (float*)d_out);
}